// round 2
// baseline (speedup 1.0000x reference)
#include <cuda_runtime.h>
#include <math.h>

// ---------------- scratch (device globals; no allocations) ----------------
#define CK 4  // k-split for gram
__device__ float g_means[2][256][1024];             // per-tensor class "sum of normalized" vectors
__device__ float g_gram[CK][2][256][256];           // partial grams (summed in listmle)
__device__ float g_rowloss[256];

// ---------------- kernel 1: fused normalize + class mean ----------------
// grid 512 (tensor*256 + class), block 256. Each thread owns 4 consecutive d's.
__global__ void means_kernel(const float* __restrict__ emb,
                             const float* __restrict__ feat) {
    int b   = blockIdx.x;
    int t   = b >> 8;
    int c   = b & 255;
    const float* x = (t == 0 ? emb : feat) + (size_t)c * 64 * 1024;
    const float4* xv = (const float4*)x;   // sample n at float4 index n*256 + tid
    int tid = threadIdx.x;

    __shared__ float red[8];
    __shared__ float s_inv;

    float4 acc = make_float4(0.f, 0.f, 0.f, 0.f);
    float4 cur = xv[tid];
    float4 nxt = xv[256 + tid];

    #pragma unroll 1
    for (int n = 0; n < 64; n++) {
        float4 after = make_float4(0.f, 0.f, 0.f, 0.f);
        if (n + 2 < 64) after = xv[(n + 2) * 256 + tid];

        float ss = cur.x * cur.x + cur.y * cur.y + cur.z * cur.z + cur.w * cur.w;
        #pragma unroll
        for (int o = 16; o; o >>= 1) ss += __shfl_xor_sync(0xffffffffu, ss, o);
        if ((tid & 31) == 0) red[tid >> 5] = ss;
        __syncthreads();
        if (tid < 8) {
            float v = red[tid];
            #pragma unroll
            for (int o = 4; o; o >>= 1) v += __shfl_xor_sync(0xffu, v, o);
            if (tid == 0) s_inv = 1.0f / fmaxf(sqrtf(v), 1e-12f);
        }
        __syncthreads();
        float inv = s_inv;
        acc.x += cur.x * inv;
        acc.y += cur.y * inv;
        acc.z += cur.z * inv;
        acc.w += cur.w * inv;
        cur = nxt;
        nxt = after;
    }
    // store SUM of normalized vectors; the /64 per factor is folded into gram (1/4096)
    ((float4*)&g_means[t][c][0])[tid] = acc;
}

// ---------------- kernel 2: gram = means @ means^T (k-split partials) ----------------
// grid (4 jtile, 4 itile, 2*CK), block 256; 64x64 tile, 4x4 register blocking.
__global__ void gram_kernel() {
    int t  = blockIdx.z >> 2;     // CK == 4
    int ks = blockIdx.z & 3;
    int i0 = blockIdx.y * 64;
    int j0 = blockIdx.x * 64;
    const float* A = &g_means[t][0][0];

    __shared__ float As[64][68];  // transposed: As[k][row]
    __shared__ float Bs[64][68];

    int tid = threadIdx.x;
    int tx = tid & 15, ty = tid >> 4;

    float acc[4][4];
    #pragma unroll
    for (int u = 0; u < 4; u++)
        #pragma unroll
        for (int v = 0; v < 4; v++) acc[u][v] = 0.f;

    int kbase = ks * 256;
    for (int kk = kbase; kk < kbase + 256; kk += 64) {
        #pragma unroll
        for (int l = 0; l < 4; l++) {
            int idx = tid + l * 256;
            int r   = idx >> 4;     // 0..63
            int f4  = idx & 15;     // 0..15
            float4 va = *(const float4*)&A[(size_t)(i0 + r) * 1024 + kk + f4 * 4];
            As[f4 * 4 + 0][r] = va.x;
            As[f4 * 4 + 1][r] = va.y;
            As[f4 * 4 + 2][r] = va.z;
            As[f4 * 4 + 3][r] = va.w;
            float4 vb = *(const float4*)&A[(size_t)(j0 + r) * 1024 + kk + f4 * 4];
            Bs[f4 * 4 + 0][r] = vb.x;
            Bs[f4 * 4 + 1][r] = vb.y;
            Bs[f4 * 4 + 2][r] = vb.z;
            Bs[f4 * 4 + 3][r] = vb.w;
        }
        __syncthreads();
        #pragma unroll
        for (int k = 0; k < 64; k++) {
            float4 a = *(const float4*)&As[k][ty * 4];
            float4 b = *(const float4*)&Bs[k][tx * 4];
            acc[0][0] += a.x * b.x; acc[0][1] += a.x * b.y; acc[0][2] += a.x * b.z; acc[0][3] += a.x * b.w;
            acc[1][0] += a.y * b.x; acc[1][1] += a.y * b.y; acc[1][2] += a.y * b.z; acc[1][3] += a.y * b.w;
            acc[2][0] += a.z * b.x; acc[2][1] += a.z * b.y; acc[2][2] += a.z * b.z; acc[2][3] += a.z * b.w;
            acc[3][0] += a.w * b.x; acc[3][1] += a.w * b.y; acc[3][2] += a.w * b.z; acc[3][3] += a.w * b.w;
        }
        __syncthreads();
    }
    const float scale = 1.0f / 4096.0f;   // (1/64)^2 from the two means
    #pragma unroll
    for (int u = 0; u < 4; u++)
        #pragma unroll
        for (int v = 0; v < 4; v++)
            g_gram[ks][t][i0 + ty * 4 + u][j0 + tx * 4 + v] = acc[u][v] * scale;
}

// ---------------- kernel 3: ListMLE per row ----------------
// grid 256 (row), block 256 (one element each).
__global__ void listmle_kernel() {
    int i = blockIdx.x, tid = threadIdx.x;
    __shared__ float tr[256];
    __shared__ float ps[256];
    __shared__ float sfx[256];
    __shared__ float red[8];

    float p = 0.f, t = 0.f;
    #pragma unroll
    for (int ks = 0; ks < CK; ks++) {
        p += g_gram[ks][0][i][tid];   // pred (embedding gram)
        t += g_gram[ks][1][i][tid];   // true (features gram)
    }
    tr[tid] = t;
    __syncthreads();

    // stable descending rank (matches jnp.argsort(-true): ties keep ascending index)
    int rank = 0;
    #pragma unroll 8
    for (int k = 0; k < 256; k++) {
        float tk = tr[k];
        rank += (tk > t) || (tk == t && k < tid);
    }
    ps[rank] = p;                      // permutation scatter
    __syncthreads();

    float psv = ps[tid];
    sfx[tid] = expf(psv);
    __syncthreads();

    // inclusive suffix sum (Hillis-Steele)
    #pragma unroll
    for (int off = 1; off < 256; off <<= 1) {
        float v = (tid + off < 256) ? sfx[tid + off] : 0.f;
        __syncthreads();
        sfx[tid] += v;
        __syncthreads();
    }

    float term = logf(sfx[tid] + 1e-10f) - psv;
    #pragma unroll
    for (int o = 16; o; o >>= 1) term += __shfl_xor_sync(0xffffffffu, term, o);
    if ((tid & 31) == 0) red[tid >> 5] = term;
    __syncthreads();
    if (tid == 0) {
        float s = 0.f;
        #pragma unroll
        for (int w = 0; w < 8; w++) s += red[w];
        g_rowloss[i] = s;
    }
}

// ---------------- kernel 4: final mean ----------------
__global__ void final_kernel(float* __restrict__ out) {
    int tid = threadIdx.x;
    __shared__ float red[8];
    float v = g_rowloss[tid];
    #pragma unroll
    for (int o = 16; o; o >>= 1) v += __shfl_xor_sync(0xffffffffu, v, o);
    if ((tid & 31) == 0) red[tid >> 5] = v;
    __syncthreads();
    if (tid == 0) {
        float s = 0.f;
        #pragma unroll
        for (int w = 0; w < 8; w++) s += red[w];
        out[0] = s * (1.0f / 256.0f);
    }
}

// ---------------- launch ----------------
extern "C" void kernel_launch(void* const* d_in, const int* in_sizes, int n_in,
                              void* d_out, int out_size) {
    const float* emb  = (const float*)d_in[0];
    const float* feat = (const float*)d_in[1];
    float* out = (float*)d_out;

    means_kernel<<<512, 256>>>(emb, feat);
    gram_kernel<<<dim3(4, 4, 2 * CK), 256>>>();
    listmle_kernel<<<256, 256>>>();
    final_kernel<<<1, 256>>>(out);
}

// round 3
// speedup vs baseline: 1.2175x; 1.2175x over previous
#include <cuda_runtime.h>
#include <math.h>

// ---------------- scratch (device globals; no allocations) ----------------
#define CK 4  // k-split for gram
__device__ float g_means[2][256][1024];    // per-tensor class "sum of normalized" vectors
__device__ float g_gram[CK][2][256][256];  // partial grams (summed in listmle)
__device__ float g_rowloss[256];
__device__ int   g_done;                   // completion counter (self-resetting)

// ---------------- kernel 1: fused normalize + class mean ----------------
// grid 512 (tensor*256 + class), block 256 = 8 warps, warp w handles samples
// [w*8, w*8+8). Lane owns float4 chunks lane + 32*j (j=0..7) of D=1024.
// Only ONE __syncthreads per block; norms reduced with warp shuffles only.
__global__ void __launch_bounds__(256) means_kernel(const float* __restrict__ emb,
                                                    const float* __restrict__ feat) {
    int b   = blockIdx.x;
    int t   = b >> 8;
    int c   = b & 255;
    const float4* xv = (const float4*)((t == 0 ? emb : feat) + (size_t)c * 64 * 1024);
    int tid  = threadIdx.x;
    int lane = tid & 31;
    int w    = tid >> 5;

    __shared__ float4 s_acc[8][256];   // 32 KB: per-warp partial mean vectors

    float4 acc[8];
    #pragma unroll
    for (int j = 0; j < 8; j++) acc[j] = make_float4(0.f, 0.f, 0.f, 0.f);

    const float4* base = xv + (size_t)(w * 8) * 256;  // this warp's 8 samples

    #pragma unroll 1
    for (int n = 0; n < 8; n++) {
        float4 cur[8];
        #pragma unroll
        for (int j = 0; j < 8; j++)
            cur[j] = base[n * 256 + j * 32 + lane];   // 8 coalesced LDG.128, MLP=8

        float ss = 0.f;
        #pragma unroll
        for (int j = 0; j < 8; j++)
            ss += cur[j].x * cur[j].x + cur[j].y * cur[j].y
                + cur[j].z * cur[j].z + cur[j].w * cur[j].w;
        #pragma unroll
        for (int o = 16; o; o >>= 1) ss += __shfl_xor_sync(0xffffffffu, ss, o);

        float inv = 1.0f / fmaxf(sqrtf(ss), 1e-12f);
        #pragma unroll
        for (int j = 0; j < 8; j++) {
            acc[j].x += cur[j].x * inv;
            acc[j].y += cur[j].y * inv;
            acc[j].z += cur[j].z * inv;
            acc[j].w += cur[j].w * inv;
        }
    }

    #pragma unroll
    for (int j = 0; j < 8; j++) s_acc[w][j * 32 + lane] = acc[j];
    __syncthreads();

    // cross-warp sum: thread tid owns float4 position tid
    float4 r = s_acc[0][tid];
    #pragma unroll
    for (int w2 = 1; w2 < 8; w2++) {
        float4 v = s_acc[w2][tid];
        r.x += v.x; r.y += v.y; r.z += v.z; r.w += v.w;
    }
    // store SUM of normalized vectors; /64 per factor folded into gram (1/4096)
    ((float4*)&g_means[t][c][0])[tid] = r;
}

// ---------------- kernel 2: gram = means @ means^T (k-split, packed f32x2 FMA) ----
// grid (4 jtile, 4 itile, 2*CK), block 256; 64x64 tile, 4x4 register blocking,
// inner loop uses fma.rn.f32x2 (FFMA2) -> half the FMA-pipe instruction count.
__global__ void __launch_bounds__(256) gram_kernel() {
    int t  = blockIdx.z >> 2;     // CK == 4
    int ks = blockIdx.z & 3;
    int i0 = blockIdx.y * 64;
    int j0 = blockIdx.x * 64;
    const float* A = &g_means[t][0][0];

    __shared__ float As[64][68];  // transposed: As[k][row]; row stride 272B (16B-mult)
    __shared__ float Bs[64][68];

    int tid = threadIdx.x;
    int tx = tid & 15, ty = tid >> 4;

    // acc[u][vpair]: packed pair of fp32 accumulators (cols tx*4+2v, tx*4+2v+1)
    unsigned long long acc[4][2];
    #pragma unroll
    for (int u = 0; u < 4; u++) { acc[u][0] = 0ull; acc[u][1] = 0ull; }

    int kbase = ks * 256;
    for (int kk = kbase; kk < kbase + 256; kk += 64) {
        #pragma unroll
        for (int l = 0; l < 4; l++) {
            int idx = tid + l * 256;
            int r   = idx >> 4;     // 0..63
            int f4  = idx & 15;     // 0..15
            float4 va = *(const float4*)&A[(size_t)(i0 + r) * 1024 + kk + f4 * 4];
            As[f4 * 4 + 0][r] = va.x;
            As[f4 * 4 + 1][r] = va.y;
            As[f4 * 4 + 2][r] = va.z;
            As[f4 * 4 + 3][r] = va.w;
            float4 vb = *(const float4*)&A[(size_t)(j0 + r) * 1024 + kk + f4 * 4];
            Bs[f4 * 4 + 0][r] = vb.x;
            Bs[f4 * 4 + 1][r] = vb.y;
            Bs[f4 * 4 + 2][r] = vb.z;
            Bs[f4 * 4 + 3][r] = vb.w;
        }
        __syncthreads();
        #pragma unroll
        for (int k = 0; k < 64; k++) {
            float4 a = *(const float4*)&As[k][ty * 4];
            ulonglong2 bv = *(const ulonglong2*)&Bs[k][tx * 4];  // (b0,b1),(b2,b3)

            unsigned long long a0, a1, a2, a3;
            asm("mov.b64 %0,{%1,%1};" : "=l"(a0) : "f"(a.x));
            asm("mov.b64 %0,{%1,%1};" : "=l"(a1) : "f"(a.y));
            asm("mov.b64 %0,{%1,%1};" : "=l"(a2) : "f"(a.z));
            asm("mov.b64 %0,{%1,%1};" : "=l"(a3) : "f"(a.w));

            asm("fma.rn.f32x2 %0,%1,%2,%0;" : "+l"(acc[0][0]) : "l"(a0), "l"(bv.x));
            asm("fma.rn.f32x2 %0,%1,%2,%0;" : "+l"(acc[0][1]) : "l"(a0), "l"(bv.y));
            asm("fma.rn.f32x2 %0,%1,%2,%0;" : "+l"(acc[1][0]) : "l"(a1), "l"(bv.x));
            asm("fma.rn.f32x2 %0,%1,%2,%0;" : "+l"(acc[1][1]) : "l"(a1), "l"(bv.y));
            asm("fma.rn.f32x2 %0,%1,%2,%0;" : "+l"(acc[2][0]) : "l"(a2), "l"(bv.x));
            asm("fma.rn.f32x2 %0,%1,%2,%0;" : "+l"(acc[2][1]) : "l"(a2), "l"(bv.y));
            asm("fma.rn.f32x2 %0,%1,%2,%0;" : "+l"(acc[3][0]) : "l"(a3), "l"(bv.x));
            asm("fma.rn.f32x2 %0,%1,%2,%0;" : "+l"(acc[3][1]) : "l"(a3), "l"(bv.y));
        }
        __syncthreads();
    }
    const float scale = 1.0f / 4096.0f;   // (1/64)^2 from the two means
    #pragma unroll
    for (int u = 0; u < 4; u++) {
        #pragma unroll
        for (int v = 0; v < 2; v++) {
            float lo, hi;
            asm("mov.b64 {%0,%1},%2;" : "=f"(lo), "=f"(hi) : "l"(acc[u][v]));
            g_gram[ks][t][i0 + ty * 4 + u][j0 + tx * 4 + 2 * v + 0] = lo * scale;
            g_gram[ks][t][i0 + ty * 4 + u][j0 + tx * 4 + 2 * v + 1] = hi * scale;
        }
    }
}

// ---------------- kernel 3: ListMLE per row + fused final mean ----------------
// grid 256 (row), block 256. Last block to finish reduces g_rowloss -> out[0].
__global__ void __launch_bounds__(256) listmle_kernel(float* __restrict__ out) {
    int i = blockIdx.x, tid = threadIdx.x;
    __shared__ float tr[256];
    __shared__ float ps[256];
    __shared__ float sfx[256];
    __shared__ float red[8];
    __shared__ int s_last;

    float p = 0.f, t = 0.f;
    #pragma unroll
    for (int ks = 0; ks < CK; ks++) {
        p += g_gram[ks][0][i][tid];   // pred (embedding gram)
        t += g_gram[ks][1][i][tid];   // true (features gram)
    }
    tr[tid] = t;
    __syncthreads();

    // stable descending rank (matches jnp.argsort(-true): ties keep ascending index)
    int rank = 0;
    #pragma unroll 8
    for (int k = 0; k < 256; k++) {
        float tk = tr[k];
        rank += (tk > t) || (tk == t && k < tid);
    }
    ps[rank] = p;                      // permutation scatter
    __syncthreads();

    float psv = ps[tid];
    sfx[tid] = expf(psv);
    __syncthreads();

    // inclusive suffix sum (Hillis-Steele)
    #pragma unroll
    for (int off = 1; off < 256; off <<= 1) {
        float v = (tid + off < 256) ? sfx[tid + off] : 0.f;
        __syncthreads();
        sfx[tid] += v;
        __syncthreads();
    }

    float term = logf(sfx[tid] + 1e-10f) - psv;
    #pragma unroll
    for (int o = 16; o; o >>= 1) term += __shfl_xor_sync(0xffffffffu, term, o);
    if ((tid & 31) == 0) red[tid >> 5] = term;
    __syncthreads();
    if (tid == 0) {
        float s = 0.f;
        #pragma unroll
        for (int w = 0; w < 8; w++) s += red[w];
        g_rowloss[i] = s;
        __threadfence();
        int v = atomicAdd(&g_done, 1);
        s_last = (v == 255);
    }
    __syncthreads();

    if (s_last) {
        // last-finishing block: reduce all row losses (deterministic fixed order)
        volatile float* rl = g_rowloss;
        float v = rl[tid];
        #pragma unroll
        for (int o = 16; o; o >>= 1) v += __shfl_xor_sync(0xffffffffu, v, o);
        if ((tid & 31) == 0) red[tid >> 5] = v;
        __syncthreads();
        if (tid == 0) {
            float s = 0.f;
            #pragma unroll
            for (int w = 0; w < 8; w++) s += red[w];
            out[0] = s * (1.0f / 256.0f);
            g_done = 0;   // self-reset for next graph replay
        }
    }
}

// ---------------- launch ----------------
extern "C" void kernel_launch(void* const* d_in, const int* in_sizes, int n_in,
                              void* d_out, int out_size) {
    const float* emb  = (const float*)d_in[0];
    const float* feat = (const float*)d_in[1];
    float* out = (float*)d_out;

    means_kernel<<<512, 256>>>(emb, feat);
    gram_kernel<<<dim3(4, 4, 2 * CK), 256>>>();
    listmle_kernel<<<256, 256>>>(out);
}